// round 5
// baseline (speedup 1.0000x reference)
#include <cuda_runtime.h>
#include <math.h>

#define FULLMASK 0xffffffffu

#define BB   2
#define NN   2048
#define HH   8
#define HID  128
#define VD   16
#define BN   (BB * NN)
// locality=5 -> pos=0.05*2047=102.35 -> need 103rd smallest (0-indexed 102)
#define KTH  103

// GEMM smem: AsT [128][66] f32 + Ws [128][64] f32
#define GEMM_SMEM ((128 * 66 + 128 * 64) * 4)
// Attention smem: full v, 2048 rows x stride-20 f32 = 160KB
#define ATTN_SMEM (NN * 20 * 4)

typedef unsigned long long ull;

// ---------------- scratch (device globals; no allocation) ----------------
__device__ float  g_en[BN * HID];
__device__ float  g_x [BN * HID];
__device__ float  g_h [BN * HID];
__device__ float  g_t [BN * HID];
__device__ float  g_r [BN * HID];
__device__ float  g_v [BN * HID];
__device__ float  g_wcat[HID * HID];
__device__ float2 g_rowstats[BN];

// ---------------- f32x2 packed helpers ----------------
__device__ __forceinline__ ull pack2(float x, float y) {
    ull r;
    asm("mov.b64 %0, {%1, %2};" : "=l"(r) : "r"(__float_as_uint(x)), "r"(__float_as_uint(y)));
    return r;
}
__device__ __forceinline__ void unpack2(ull u, float& x, float& y) {
    unsigned a, b;
    asm("mov.b64 {%0, %1}, %2;" : "=r"(a), "=r"(b) : "l"(u));
    x = __uint_as_float(a); y = __uint_as_float(b);
}
__device__ __forceinline__ ull fma2(ull a, ull b, ull c) {
    ull d;
    asm("fma.rn.f32x2 %0, %1, %2, %3;" : "=l"(d) : "l"(a), "l"(b), "l"(c));
    return d;
}
__device__ __forceinline__ ull add2(ull a, ull b) {
    ull d;
    asm("add.rn.f32x2 %0, %1, %2;" : "=l"(d) : "l"(a), "l"(b));
    return d;
}
__device__ __forceinline__ float ex2f(float x) {
    float r;
    asm("ex2.approx.f32 %0, %1;" : "=f"(r) : "f"(x));
    return r;
}

__device__ __forceinline__ float gelu_f(float x) {
    // exact (erf) gelu, matching jax.nn.gelu(approximate=False)
    return 0.5f * x * (1.0f + erff(x * 0.70710678118654752f));
}

// ---------------- per-row order statistics of m_dist ----------------
// For each of the B*N rows (length N): min and the 103rd-smallest value.
// Monotone m -> m*r^2 makes these sufficient for softmax max and the
// percentile mask of both masked mhpas, all heads. Exact selection via
// binary search on the nonnegative-float bit pattern (values in [0,1)).
__global__ void rowstats_kernel(const float* __restrict__ md, float2* __restrict__ rs) {
    int warp = threadIdx.x >> 5, lane = threadIdx.x & 31;
    int row = blockIdx.x * 8 + warp;
    const float* p = md + (size_t)row * NN + lane;
    unsigned mu[64];
    float mn = 1e30f;
#pragma unroll
    for (int i = 0; i < 64; ++i) {
        float x = p[i * 32];
        mn = fminf(mn, x);
        mu[i] = __float_as_uint(x);
    }
#pragma unroll
    for (int off = 16; off; off >>= 1)
        mn = fminf(mn, __shfl_xor_sync(FULLMASK, mn, off));

    unsigned lo = 0u, hi = 0x3F800000u;  // bit patterns of [0,1)
    while (hi - lo > 1u) {
        unsigned mid = (lo + hi) >> 1;
        int c = 0;
#pragma unroll
        for (int i = 0; i < 64; ++i) c += (mu[i] <= mid) ? 1 : 0;
        c = __reduce_add_sync(FULLMASK, c);
        if (c >= KTH) hi = mid; else lo = mid;
    }
    if (lane == 0) rs[row] = make_float2(mn, __uint_as_float(hi));
}

// ---------------- encoder: gelu(inputs @ en_W + en_b), K=3 ----------------
__global__ void enc_kernel(const float* __restrict__ inp, const float* __restrict__ W,
                           const float* __restrict__ bvec, float* __restrict__ out) {
    int token = blockIdx.x, c = threadIdx.x;
    float x0 = inp[token * 3 + 0];
    float x1 = inp[token * 3 + 1];
    float x2 = inp[token * 3 + 2];
    float s = bvec[c];
    s = fmaf(x0, W[c], s);
    s = fmaf(x1, W[HID + c], s);
    s = fmaf(x2, W[2 * HID + c], s);
    out[(size_t)token * HID + c] = gelu_f(s);
}

// ---------------- repack head weights (H,HID,VD) -> (HID, H*VD) ----------------
__global__ void repack_kernel(const float* __restrict__ w, float* __restrict__ wc) {
    int idx = blockIdx.x * 256 + threadIdx.x;  // 16384 total
    int k = idx >> 7, c = idx & 127;
    wc[idx] = w[(c >> 4) * (HID * VD) + k * VD + (c & 15)];
}

// ---------------- 4096x128 @ 128x128 GEMM, tiled 64 rows x 64 cols ---------
// Grid (BN/64, 2), 256 threads. A staged TRANSPOSED in smem [k][row] (stride
// 66: conflict-free STS, even for aligned LDS.64). Warp owns 8 rows as 4
// row-pairs; lane owns col pair (2l, 2l+1). Per k per thread: 1 LDS.64 (w
// pair) + 4 broadcast LDS.64 (a row-pairs) + 2 packs + 8 FMA2 (16 MACs).
// k-loop software-pipelined by 1 to cover LDS latency.
__global__ void __launch_bounds__(256) gemm4_kernel(
    const float* __restrict__ A, const float* __restrict__ W,
    const float* __restrict__ bias, const float* __restrict__ res,
    float* __restrict__ out, int act)
{
    extern __shared__ float sm[];
    float* AsT = sm;             // [128 k][66]
    float* Ws  = sm + 128 * 66;  // [128 k][64]

    int tid = threadIdx.x, lane = tid & 31, warp = tid >> 5;
    int row0 = blockIdx.x * 64;
    int cbase = blockIdx.y * 64;

    // stage W half: [k][64]
#pragma unroll
    for (int idx = tid; idx < 128 * 16; idx += 256) {
        int k = idx >> 4, q = idx & 15;
        *(float4*)(Ws + k * 64 + q * 4) = *(const float4*)(W + (size_t)k * HID + cbase + q * 4);
    }
    // stage A transposed: thread (r = tid&63, kq = (tid>>6)*32) covers 32 k
    {
        int r = tid & 63;
        int kq = (tid >> 6) << 5;
        const float* ap = A + (size_t)(row0 + r) * HID + kq;
#pragma unroll
        for (int i = 0; i < 8; ++i) {
            float4 a = *(const float4*)(ap + 4 * i);
            int k = kq + 4 * i;
            AsT[(k + 0) * 66 + r] = a.x;
            AsT[(k + 1) * 66 + r] = a.y;
            AsT[(k + 2) * 66 + r] = a.z;
            AsT[(k + 3) * 66 + r] = a.w;
        }
    }
    __syncthreads();

    ull acc[4][2];
#pragma unroll
    for (int p = 0; p < 4; ++p) { acc[p][0] = 0ull; acc[p][1] = 0ull; }

    const float* wp0 = Ws + 2 * lane;
    const ull*   ap0 = (const ull*)(AsT + warp * 8);   // stride 33 ull per k

    // pipeline: preload k=0
    float2 wf = *(const float2*)(wp0);
    ull a0 = ap0[0], a1 = ap0[1], a2 = ap0[2], a3 = ap0[3];

#pragma unroll 4
    for (int k = 0; k < HID; ++k) {
        float2 wfn;
        ull n0, n1, n2, n3;
        if (k < HID - 1) {
            wfn = *(const float2*)(wp0 + (k + 1) * 64);
            const ull* an = ap0 + (k + 1) * 33;
            n0 = an[0]; n1 = an[1]; n2 = an[2]; n3 = an[3];
        }
        ull wc0 = pack2(wf.x, wf.x);
        ull wc1 = pack2(wf.y, wf.y);
        acc[0][0] = fma2(a0, wc0, acc[0][0]);  acc[0][1] = fma2(a0, wc1, acc[0][1]);
        acc[1][0] = fma2(a1, wc0, acc[1][0]);  acc[1][1] = fma2(a1, wc1, acc[1][1]);
        acc[2][0] = fma2(a2, wc0, acc[2][0]);  acc[2][1] = fma2(a2, wc1, acc[2][1]);
        acc[3][0] = fma2(a3, wc0, acc[3][0]);  acc[3][1] = fma2(a3, wc1, acc[3][1]);
        if (k < HID - 1) { wf = wfn; a0 = n0; a1 = n1; a2 = n2; a3 = n3; }
    }

    float b0 = 0.f, b1 = 0.f;
    if (bias) {
        float2 bv = *(const float2*)(bias + cbase + 2 * lane);
        b0 = bv.x; b1 = bv.y;
    }
#pragma unroll
    for (int p = 0; p < 4; ++p) {
        float oc0r0, oc0r1, oc1r0, oc1r1;
        unpack2(acc[p][0], oc0r0, oc0r1);
        unpack2(acc[p][1], oc1r0, oc1r1);
        int rowA = row0 + warp * 8 + 2 * p;
        float o00 = oc0r0 + b0, o01 = oc1r0 + b1;   // row 2p
        float o10 = oc0r1 + b0, o11 = oc1r1 + b1;   // row 2p+1
        if (res) {
            float2 rA = *(const float2*)(res + (size_t)rowA * HID + cbase + 2 * lane);
            float2 rB = *(const float2*)(res + (size_t)(rowA + 1) * HID + cbase + 2 * lane);
            o00 += rA.x; o01 += rA.y; o10 += rB.x; o11 += rB.y;
        }
        if (act) { o00 = gelu_f(o00); o01 = gelu_f(o01); o10 = gelu_f(o10); o11 = gelu_f(o11); }
        *(float2*)(out + (size_t)rowA * HID + cbase + 2 * lane)       = make_float2(o00, o01);
        *(float2*)(out + (size_t)(rowA + 1) * HID + cbase + 2 * lane) = make_float2(o10, o11);
    }
}

// ---------------- fused percentile-softmax attention + gelu ----------------
// CTA: 256 threads = 8 warps x 4 rows = 32 rows, one (b,h). Full v (2048x16)
// in smem, stride 20 (16B-aligned rows -> LDS.128, conflict-free). Lane <-> j
// with depth-4 prefetch ring on m_dist (covers ~260cyc L2 latency). exp once
// per (i,j); 16 dims as 8 packed f32x2 FMAs; v bytes amortized over 4 rows
// (1B/MAC = crossbar balance point).
template <int MASKED>
__global__ void __launch_bounds__(256, 1) attn4_kernel(
    const float* __restrict__ md, const float* __restrict__ v,
    const float* __restrict__ rvec, const float2* __restrict__ rs,
    float* __restrict__ out)
{
    extern __shared__ float vs[];   // [2048][20]
    int b = blockIdx.z, h = blockIdx.y;
    float rr = rvec[h];
    float r2 = rr * rr;
    const float L2E = 1.4426950408889634f;
    float nr2l = -r2 * L2E;

    int tid = threadIdx.x;
    int lane = tid & 31, warp = tid >> 5;
    int i0 = blockIdx.x * 32 + warp * 4;

    // stage full v_h into smem
    const float* vg = v + (size_t)b * NN * HID + h * VD;
    for (int idx = tid; idx < NN * 8; idx += 256) {
        int jj = idx >> 3, dd = (idx & 7) << 1;
        float2 val = *(const float2*)(vg + (size_t)jj * HID + dd);
        *(float2*)(vs + jj * 20 + dd) = val;
    }

    float msdl[4], s102[4], wsum[4];
    ull acc[4][8];
#pragma unroll
    for (int g = 0; g < 4; ++g) {
        float2 st = rs[b * NN + i0 + g];
        msdl[g] = (st.x * r2) * L2E;  // st.x*r2 == min_j(sd) exactly (monotone)
        s102[g] = st.y;
        wsum[g] = 0.f;
#pragma unroll
        for (int d = 0; d < 8; ++d) acc[g][d] = 0ull;
    }

    const float* mrow = md + ((size_t)b * NN + i0) * NN + lane;

    __syncthreads();

    // prime depth-4 prefetch ring
    float mr[4][4];
#pragma unroll
    for (int d = 0; d < 4; ++d)
#pragma unroll
        for (int g = 0; g < 4; ++g) mr[g][d] = mrow[(size_t)g * NN + 32 * d];

#pragma unroll 2
    for (int t = 0; t < NN / 32; ++t) {
        int slot = t & 3;
        int j = lane + 32 * t;

        const ulonglong2* vrow = (const ulonglong2*)(vs + j * 20);
        ulonglong2 va = vrow[0], vb2 = vrow[1];
        ull v0 = va.x,  v1 = va.y,  v2 = vb2.x, v3 = vb2.y;
        ulonglong2 vc = vrow[2], vd = vrow[3];
        ull v4 = vc.x,  v5 = vc.y,  v6 = vd.x,  v7 = vd.y;

        float m0 = mr[0][slot], m1 = mr[1][slot], m2 = mr[2][slot], m3 = mr[3][slot];

        // prefetch step t+4 (clamped; redundant tail prefetches are unused)
        int tp = t + 4; if (tp > NN / 32 - 1) tp = NN / 32 - 1;
        mr[0][slot] = mrow[0 * (size_t)NN + 32 * tp];
        mr[1][slot] = mrow[1 * (size_t)NN + 32 * tp];
        mr[2][slot] = mrow[2 * (size_t)NN + 32 * tp];
        mr[3][slot] = mrow[3 * (size_t)NN + 32 * tp];

        float mm[4] = {m0, m1, m2, m3};
#pragma unroll
        for (int g = 0; g < 4; ++g) {
            float m = mm[g];
            float e = ex2f(fmaf(m, nr2l, msdl[g]));
            float w = MASKED ? ((m <= s102[g]) ? e : 0.f) : e;
            wsum[g] += w;
            ull wp = pack2(w, w);
            acc[g][0] = fma2(wp, v0, acc[g][0]);
            acc[g][1] = fma2(wp, v1, acc[g][1]);
            acc[g][2] = fma2(wp, v2, acc[g][2]);
            acc[g][3] = fma2(wp, v3, acc[g][3]);
            acc[g][4] = fma2(wp, v4, acc[g][4]);
            acc[g][5] = fma2(wp, v5, acc[g][5]);
            acc[g][6] = fma2(wp, v6, acc[g][6]);
            acc[g][7] = fma2(wp, v7, acc[g][7]);
        }
    }

    // butterfly reduce across 32 lanes (j slots)
#pragma unroll
    for (int off = 16; off; off >>= 1) {
#pragma unroll
        for (int g = 0; g < 4; ++g) {
            wsum[g] += __shfl_xor_sync(FULLMASK, wsum[g], off);
#pragma unroll
            for (int d = 0; d < 8; ++d) {
                ull o = __shfl_xor_sync(FULLMASK, acc[g][d], off);
                acc[g][d] = add2(acc[g][d], o);
            }
        }
    }

    if (lane < 4) {
        int g = lane;
        float inv = 1.0f / wsum[g];
        float o[16];
#pragma unroll
        for (int d = 0; d < 8; ++d) unpack2(acc[g][d], o[2 * d], o[2 * d + 1]);
#pragma unroll
        for (int e = 0; e < 16; ++e) o[e] = gelu_f(o[e] * inv);
        float* dst = out + (size_t)(b * NN + i0 + g) * HID + h * VD;
        *(float4*)(dst + 0)  = make_float4(o[0],  o[1],  o[2],  o[3]);
        *(float4*)(dst + 4)  = make_float4(o[4],  o[5],  o[6],  o[7]);
        *(float4*)(dst + 8)  = make_float4(o[8],  o[9],  o[10], o[11]);
        *(float4*)(dst + 12) = make_float4(o[12], o[13], o[14], o[15]);
    }
}

// ---------------- final 128 -> 1 projection ----------------
__global__ void final_kernel(const float* __restrict__ t, const float* __restrict__ W,
                             const float* __restrict__ bvec, float* __restrict__ out) {
    int warp = threadIdx.x >> 5, lane = threadIdx.x & 31;
    int token = blockIdx.x * 8 + warp;
    const float* p = t + (size_t)token * HID;
    float s = 0.f;
#pragma unroll
    for (int i = 0; i < 4; ++i) s = fmaf(p[lane + 32 * i], W[lane + 32 * i], s);
#pragma unroll
    for (int off = 16; off; off >>= 1) s += __shfl_xor_sync(FULLMASK, s, off);
    if (lane == 0) out[token] = s + bvec[0];
}

// ---------------- orchestration ----------------
static float* symf(const void* sym) {
    void* p = nullptr;
    cudaGetSymbolAddress(&p, sym);
    return (float*)p;
}

extern "C" void kernel_launch(void* const* d_in, const int* in_sizes, int n_in,
                              void* d_out, int out_size) {
    const float* md      = (const float*)d_in[0];
    const float* inputs  = (const float*)d_in[1];
    const float* en_W    = (const float*)d_in[2];
    const float* en_b    = (const float*)d_in[3];
    const float* down_r  = (const float*)d_in[4];
    const float* down_w  = (const float*)d_in[5];
    const float* mlp1_W1 = (const float*)d_in[6];
    const float* mlp1_b1 = (const float*)d_in[7];
    const float* mlp1_W2 = (const float*)d_in[8];
    const float* mlp1_b2 = (const float*)d_in[9];
    const float* w1_W    = (const float*)d_in[10];
    const float* w1_b    = (const float*)d_in[11];
    const float* pa_r    = (const float*)d_in[12];
    const float* pa_w    = (const float*)d_in[13];
    const float* blk_W1  = (const float*)d_in[14];
    const float* blk_b1  = (const float*)d_in[15];
    const float* blk_W2  = (const float*)d_in[16];
    const float* blk_b2  = (const float*)d_in[17];
    const float* wi_W    = (const float*)d_in[18];
    const float* wi_b    = (const float*)d_in[19];
    const float* up_r    = (const float*)d_in[20];
    const float* up_w    = (const float*)d_in[21];
    const float* mlp2_W1 = (const float*)d_in[22];
    const float* mlp2_b1 = (const float*)d_in[23];
    const float* mlp2_W2 = (const float*)d_in[24];
    const float* mlp2_b2 = (const float*)d_in[25];
    const float* w2_W    = (const float*)d_in[26];
    const float* w2_b    = (const float*)d_in[27];
    const float* de_W1   = (const float*)d_in[28];
    const float* de_b1   = (const float*)d_in[29];
    const float* de_W2   = (const float*)d_in[30];
    const float* de_b2   = (const float*)d_in[31];
    float* outp = (float*)d_out;

    float*  en = symf(g_en);
    float*  x  = symf(g_x);
    float*  hb = symf(g_h);
    float*  tb = symf(g_t);
    float*  rb = symf(g_r);
    float*  vb = symf(g_v);
    float*  wc = symf(g_wcat);
    float2* rsp;
    { void* p = nullptr; cudaGetSymbolAddress(&p, g_rowstats); rsp = (float2*)p; }

    cudaFuncSetAttribute(gemm4_kernel, cudaFuncAttributeMaxDynamicSharedMemorySize, GEMM_SMEM);
    cudaFuncSetAttribute(attn4_kernel<0>, cudaFuncAttributeMaxDynamicSharedMemorySize, ATTN_SMEM);
    cudaFuncSetAttribute(attn4_kernel<1>, cudaFuncAttributeMaxDynamicSharedMemorySize, ATTN_SMEM);

    dim3 ggrid(BN / 64, 2);
    dim3 agrid(NN / 32, HH, BB);

    rowstats_kernel<<<BN / 8, 256>>>(md, rsp);
    enc_kernel<<<BN, HID>>>(inputs, en_W, en_b, en);

    // ---- stage 1 (input en, masked mhpa) ----
    // launch order keeps attn as the 6th launch so ncu -s 5 captures it
    repack_kernel<<<64, 256>>>(down_w, wc);
    gemm4_kernel<<<ggrid, 256, GEMM_SMEM>>>(en, wc, nullptr, nullptr, vb, 0);
    gemm4_kernel<<<ggrid, 256, GEMM_SMEM>>>(en, w1_W, w1_b, nullptr, rb, 0);
    attn4_kernel<1><<<agrid, 256, ATTN_SMEM>>>(md, vb, down_r, rsp, hb);
    gemm4_kernel<<<ggrid, 256, GEMM_SMEM>>>(hb, mlp1_W1, mlp1_b1, nullptr, tb, 1);
    gemm4_kernel<<<ggrid, 256, GEMM_SMEM>>>(tb, mlp1_W2, mlp1_b2, rb, x, 1);

    // ---- 4 unmasked blocks ----
    for (int i = 0; i < 4; ++i) {
        repack_kernel<<<64, 256>>>(pa_w + (size_t)i * HH * HID * VD, wc);
        gemm4_kernel<<<ggrid, 256, GEMM_SMEM>>>(x, wc, nullptr, nullptr, vb, 0);
        gemm4_kernel<<<ggrid, 256, GEMM_SMEM>>>(x, wi_W + (size_t)i * HID * HID, wi_b + (size_t)i * HID, nullptr, rb, 0);
        attn4_kernel<0><<<agrid, 256, ATTN_SMEM>>>(md, vb, pa_r + (size_t)i * HH, rsp, hb);
        gemm4_kernel<<<ggrid, 256, GEMM_SMEM>>>(hb, blk_W1 + (size_t)i * HID * HID, blk_b1 + (size_t)i * HID, nullptr, tb, 1);
        gemm4_kernel<<<ggrid, 256, GEMM_SMEM>>>(tb, blk_W2 + (size_t)i * HID * HID, blk_b2 + (size_t)i * HID, rb, x, 1);
    }

    // ---- stage 2 (masked mhpa) ----
    repack_kernel<<<64, 256>>>(up_w, wc);
    gemm4_kernel<<<ggrid, 256, GEMM_SMEM>>>(x, wc, nullptr, nullptr, vb, 0);
    gemm4_kernel<<<ggrid, 256, GEMM_SMEM>>>(x, w2_W, w2_b, nullptr, rb, 0);
    attn4_kernel<1><<<agrid, 256, ATTN_SMEM>>>(md, vb, up_r, rsp, hb);
    gemm4_kernel<<<ggrid, 256, GEMM_SMEM>>>(hb, mlp2_W1, mlp2_b1, nullptr, tb, 1);
    gemm4_kernel<<<ggrid, 256, GEMM_SMEM>>>(tb, mlp2_W2, mlp2_b2, rb, x, 1);   // x = de

    // ---- decoder ----
    gemm4_kernel<<<ggrid, 256, GEMM_SMEM>>>(x, de_W1, de_b1, nullptr, tb, 1);
    final_kernel<<<BN / 8, 256>>>(tb, de_W2, de_b2, outp);
}

// round 6
// speedup vs baseline: 1.3453x; 1.3453x over previous
#include <cuda_runtime.h>
#include <math.h>

#define FULLMASK 0xffffffffu

#define BB   2
#define NN   2048
#define HH   8
#define HID  128
#define VD   16
#define BN   (BB * NN)
// locality=5 -> pos=0.05*2047=102.35 -> need 103rd smallest (0-indexed 102)
#define KTH  103

// GEMM smem: Ws [128][64] f32 (32KB) + As [32][128] f32 (16KB) = 48KB
#define GEMM_SMEM (32768 + 16384)
// Attention smem: full v, 2048 rows x stride-20 f32 = 160KB
#define ATTN_SMEM (NN * 20 * 4)

typedef unsigned long long ull;

// ---------------- scratch (device globals; no allocation) ----------------
__device__ float  g_en[BN * HID];
__device__ float  g_x [BN * HID];
__device__ float  g_h [BN * HID];
__device__ float  g_t [BN * HID];
__device__ float  g_r [BN * HID];
__device__ float  g_v [BN * HID];
__device__ float  g_wcat[HID * HID];
__device__ float2 g_rowstats[BN];

// ---------------- f32x2 packed helpers ----------------
__device__ __forceinline__ ull pack2(float x, float y) {
    ull r;
    asm("mov.b64 %0, {%1, %2};" : "=l"(r) : "r"(__float_as_uint(x)), "r"(__float_as_uint(y)));
    return r;
}
__device__ __forceinline__ void unpack2(ull u, float& x, float& y) {
    unsigned a, b;
    asm("mov.b64 {%0, %1}, %2;" : "=r"(a), "=r"(b) : "l"(u));
    x = __uint_as_float(a); y = __uint_as_float(b);
}
__device__ __forceinline__ ull fma2(ull a, ull b, ull c) {
    ull d;
    asm("fma.rn.f32x2 %0, %1, %2, %3;" : "=l"(d) : "l"(a), "l"(b), "l"(c));
    return d;
}
__device__ __forceinline__ ull add2(ull a, ull b) {
    ull d;
    asm("add.rn.f32x2 %0, %1, %2;" : "=l"(d) : "l"(a), "l"(b));
    return d;
}
__device__ __forceinline__ float ex2f(float x) {
    float r;
    asm("ex2.approx.f32 %0, %1;" : "=f"(r) : "f"(x));
    return r;
}

__device__ __forceinline__ float gelu_f(float x) {
    // exact (erf) gelu, matching jax.nn.gelu(approximate=False)
    return 0.5f * x * (1.0f + erff(x * 0.70710678118654752f));
}

// ---------------- per-row order statistics of m_dist ----------------
__global__ void rowstats_kernel(const float* __restrict__ md, float2* __restrict__ rs) {
    int warp = threadIdx.x >> 5, lane = threadIdx.x & 31;
    int row = blockIdx.x * 8 + warp;
    const float* p = md + (size_t)row * NN + lane;
    unsigned mu[64];
    float mn = 1e30f;
#pragma unroll
    for (int i = 0; i < 64; ++i) {
        float x = p[i * 32];
        mn = fminf(mn, x);
        mu[i] = __float_as_uint(x);
    }
#pragma unroll
    for (int off = 16; off; off >>= 1)
        mn = fminf(mn, __shfl_xor_sync(FULLMASK, mn, off));

    unsigned lo = 0u, hi = 0x3F800000u;  // bit patterns of [0,1)
    while (hi - lo > 1u) {
        unsigned mid = (lo + hi) >> 1;
        int c = 0;
#pragma unroll
        for (int i = 0; i < 64; ++i) c += (mu[i] <= mid) ? 1 : 0;
        c = __reduce_add_sync(FULLMASK, c);
        if (c >= KTH) hi = mid; else lo = mid;
    }
    if (lane == 0) rs[row] = make_float2(mn, __uint_as_float(hi));
}

// ---------------- encoder: gelu(inputs @ en_W + en_b), K=3 ----------------
__global__ void enc_kernel(const float* __restrict__ inp, const float* __restrict__ W,
                           const float* __restrict__ bvec, float* __restrict__ out) {
    int token = blockIdx.x, c = threadIdx.x;
    float x0 = inp[token * 3 + 0];
    float x1 = inp[token * 3 + 1];
    float x2 = inp[token * 3 + 2];
    float s = bvec[c];
    s = fmaf(x0, W[c], s);
    s = fmaf(x1, W[HID + c], s);
    s = fmaf(x2, W[2 * HID + c], s);
    out[(size_t)token * HID + c] = gelu_f(s);
}

// ---------------- repack head weights (H,HID,VD) -> (HID, H*VD) ----------------
__global__ void repack_kernel(const float* __restrict__ w, float* __restrict__ wc) {
    int idx = blockIdx.x * 256 + threadIdx.x;  // 16384 total
    int k = idx >> 7, c = idx & 127;
    wc[idx] = w[(c >> 4) * (HID * VD) + k * VD + (c & 15)];
}

// ---------------- GEMM body: 32 rows x 64 cols per CTA (R4's gemm3) -------
__device__ __forceinline__ void gemm3_body(
    const float* __restrict__ A, const float* __restrict__ W,
    const float* __restrict__ bias, const float* __restrict__ res,
    float* __restrict__ out, int act, float* sm)
{
    float* Ws = sm;              // [128][64]
    float* As = sm + 128 * 64;   // [32][128]

    int tid = threadIdx.x, lane = tid & 31, warp = tid >> 5;
    int row0 = blockIdx.x * 32;
    int cbase = blockIdx.y * 64;

#pragma unroll
    for (int idx = tid; idx < 128 * 16; idx += 256) {
        int k = idx >> 4, q = idx & 15;
        *(float4*)(Ws + k * 64 + q * 4) = *(const float4*)(W + (size_t)k * HID + cbase + q * 4);
    }
#pragma unroll
    for (int idx = tid; idx < 32 * 32; idx += 256) {
        int r = idx >> 5, q = idx & 31;
        *(float4*)(As + r * HID + q * 4) = *(const float4*)(A + (size_t)(row0 + r) * HID + q * 4);
    }
    __syncthreads();

    ull acc[4] = {0ull, 0ull, 0ull, 0ull};
    const ull* Wu = (const ull*)Ws;          // [k][32]
    const float* a0 = As + warp * 4 * HID;

#pragma unroll 8
    for (int k = 0; k < HID; ++k) {
        ull wp = Wu[k * 32 + lane];
        float x0 = a0[0 * HID + k];
        float x1 = a0[1 * HID + k];
        float x2 = a0[2 * HID + k];
        float x3 = a0[3 * HID + k];
        acc[0] = fma2(pack2(x0, x0), wp, acc[0]);
        acc[1] = fma2(pack2(x1, x1), wp, acc[1]);
        acc[2] = fma2(pack2(x2, x2), wp, acc[2]);
        acc[3] = fma2(pack2(x3, x3), wp, acc[3]);
    }

    float b0 = 0.f, b1 = 0.f;
    if (bias) {
        float2 bv = *(const float2*)(bias + cbase + 2 * lane);
        b0 = bv.x; b1 = bv.y;
    }
#pragma unroll
    for (int i = 0; i < 4; ++i) {
        int row = row0 + warp * 4 + i;
        float o0, o1;
        unpack2(acc[i], o0, o1);
        o0 += b0; o1 += b1;
        if (res) {
            float2 rv = *(const float2*)(res + (size_t)row * HID + cbase + 2 * lane);
            o0 += rv.x; o1 += rv.y;
        }
        if (act) { o0 = gelu_f(o0); o1 = gelu_f(o1); }
        *(float2*)(out + (size_t)row * HID + cbase + 2 * lane) = make_float2(o0, o1);
    }
}

__global__ void __launch_bounds__(256) gemm3_kernel(
    const float* __restrict__ A, const float* __restrict__ W,
    const float* __restrict__ bias, const float* __restrict__ res,
    float* __restrict__ out, int act)
{
    extern __shared__ float sm[];
    gemm3_body(A, W, bias, res, out, act, sm);
}

// paired GEMM: two weight sets on the same A, selected by blockIdx.z.
// z=0: out0 = A@W0 (no bias, no act). z=1: out1 = A@W1 + b1 (no act).
__global__ void __launch_bounds__(256) gemm3p_kernel(
    const float* __restrict__ A,
    const float* __restrict__ W0, float* __restrict__ out0,
    const float* __restrict__ W1, const float* __restrict__ b1,
    float* __restrict__ out1)
{
    extern __shared__ float sm[];
    if (blockIdx.z == 0) gemm3_body(A, W0, nullptr, nullptr, out0, 0, sm);
    else                 gemm3_body(A, W1, b1,      nullptr, out1, 0, sm);
}

// ---------------- fused percentile-softmax attention + gelu ----------------
// CTA: 512 threads = 16 warps x 4 rows = 64 rows, one (b,h). Full v (2048x16)
// in smem, stride 20 (16B-aligned rows -> LDS.128; quarter-warp bank starts
// {0,20,8,28,16,4,24,12} cover all banks -> conflict-free). Lane <-> j with
// depth-2 prefetch ring on m_dist. exp once per (i,j); 16 dims as 8 packed
// f32x2 FMAs; v bytes amortized over 4 rows (1B/MAC crossbar balance).
template <int MASKED>
__global__ void __launch_bounds__(512, 1) attn5_kernel(
    const float* __restrict__ md, const float* __restrict__ v,
    const float* __restrict__ rvec, const float2* __restrict__ rs,
    float* __restrict__ out)
{
    extern __shared__ float vs[];   // [2048][20]
    int b = blockIdx.z, h = blockIdx.y;
    float rr = rvec[h];
    float r2 = rr * rr;
    const float L2E = 1.4426950408889634f;
    float nr2l = -r2 * L2E;

    int tid = threadIdx.x;
    int lane = tid & 31, warp = tid >> 5;
    int i0 = blockIdx.x * 64 + warp * 4;

    // stage full v_h into smem
    const float* vg = v + (size_t)b * NN * HID + h * VD;
    for (int idx = tid; idx < NN * 8; idx += 512) {
        int jj = idx >> 3, dd = (idx & 7) << 1;
        float2 val = *(const float2*)(vg + (size_t)jj * HID + dd);
        *(float2*)(vs + jj * 20 + dd) = val;
    }

    float msdl[4], s102[4], wsum[4];
    ull acc[4][8];
#pragma unroll
    for (int g = 0; g < 4; ++g) {
        float2 st = rs[b * NN + i0 + g];
        msdl[g] = (st.x * r2) * L2E;  // st.x*r2 == min_j(sd) exactly (monotone)
        s102[g] = st.y;
        wsum[g] = 0.f;
#pragma unroll
        for (int d = 0; d < 8; ++d) acc[g][d] = 0ull;
    }

    const float* mrow = md + ((size_t)b * NN + i0) * NN + lane;

    __syncthreads();

    // prime depth-2 prefetch ring
    float mr[4][2];
#pragma unroll
    for (int d = 0; d < 2; ++d)
#pragma unroll
        for (int g = 0; g < 4; ++g) mr[g][d] = mrow[(size_t)g * NN + 32 * d];

#pragma unroll 2
    for (int t = 0; t < NN / 32; ++t) {
        int slot = t & 1;
        int j = lane + 32 * t;

        const ulonglong2* vrow = (const ulonglong2*)(vs + j * 20);
        ulonglong2 va = vrow[0], vb2 = vrow[1];
        ull v0 = va.x,  v1 = va.y,  v2 = vb2.x, v3 = vb2.y;
        ulonglong2 vc = vrow[2], vd = vrow[3];
        ull v4 = vc.x,  v5 = vc.y,  v6 = vd.x,  v7 = vd.y;

        float m0 = mr[0][slot], m1 = mr[1][slot], m2 = mr[2][slot], m3 = mr[3][slot];

        // prefetch step t+2 (clamped; redundant tail prefetches unused)
        int tp = t + 2; if (tp > NN / 32 - 1) tp = NN / 32 - 1;
        mr[0][slot] = mrow[0 * (size_t)NN + 32 * tp];
        mr[1][slot] = mrow[1 * (size_t)NN + 32 * tp];
        mr[2][slot] = mrow[2 * (size_t)NN + 32 * tp];
        mr[3][slot] = mrow[3 * (size_t)NN + 32 * tp];

        float mm[4] = {m0, m1, m2, m3};
#pragma unroll
        for (int g = 0; g < 4; ++g) {
            float m = mm[g];
            float e = ex2f(fmaf(m, nr2l, msdl[g]));
            float w = MASKED ? ((m <= s102[g]) ? e : 0.f) : e;
            wsum[g] += w;
            ull wp = pack2(w, w);
            acc[g][0] = fma2(wp, v0, acc[g][0]);
            acc[g][1] = fma2(wp, v1, acc[g][1]);
            acc[g][2] = fma2(wp, v2, acc[g][2]);
            acc[g][3] = fma2(wp, v3, acc[g][3]);
            acc[g][4] = fma2(wp, v4, acc[g][4]);
            acc[g][5] = fma2(wp, v5, acc[g][5]);
            acc[g][6] = fma2(wp, v6, acc[g][6]);
            acc[g][7] = fma2(wp, v7, acc[g][7]);
        }
    }

    // butterfly reduce across 32 lanes (j slots)
#pragma unroll
    for (int off = 16; off; off >>= 1) {
#pragma unroll
        for (int g = 0; g < 4; ++g) {
            wsum[g] += __shfl_xor_sync(FULLMASK, wsum[g], off);
#pragma unroll
            for (int d = 0; d < 8; ++d) {
                ull o = __shfl_xor_sync(FULLMASK, acc[g][d], off);
                acc[g][d] = add2(acc[g][d], o);
            }
        }
    }

    if (lane < 4) {
        int g = lane;
        float inv = 1.0f / wsum[g];
        float o[16];
#pragma unroll
        for (int d = 0; d < 8; ++d) unpack2(acc[g][d], o[2 * d], o[2 * d + 1]);
#pragma unroll
        for (int e = 0; e < 16; ++e) o[e] = gelu_f(o[e] * inv);
        float* dst = out + (size_t)(b * NN + i0 + g) * HID + h * VD;
        *(float4*)(dst + 0)  = make_float4(o[0],  o[1],  o[2],  o[3]);
        *(float4*)(dst + 4)  = make_float4(o[4],  o[5],  o[6],  o[7]);
        *(float4*)(dst + 8)  = make_float4(o[8],  o[9],  o[10], o[11]);
        *(float4*)(dst + 12) = make_float4(o[12], o[13], o[14], o[15]);
    }
}

// ---------------- final 128 -> 1 projection ----------------
__global__ void final_kernel(const float* __restrict__ t, const float* __restrict__ W,
                             const float* __restrict__ bvec, float* __restrict__ out) {
    int warp = threadIdx.x >> 5, lane = threadIdx.x & 31;
    int token = blockIdx.x * 8 + warp;
    const float* p = t + (size_t)token * HID;
    float s = 0.f;
#pragma unroll
    for (int i = 0; i < 4; ++i) s = fmaf(p[lane + 32 * i], W[lane + 32 * i], s);
#pragma unroll
    for (int off = 16; off; off >>= 1) s += __shfl_xor_sync(FULLMASK, s, off);
    if (lane == 0) out[token] = s + bvec[0];
}

// ---------------- orchestration ----------------
static float* symf(const void* sym) {
    void* p = nullptr;
    cudaGetSymbolAddress(&p, sym);
    return (float*)p;
}

extern "C" void kernel_launch(void* const* d_in, const int* in_sizes, int n_in,
                              void* d_out, int out_size) {
    const float* md      = (const float*)d_in[0];
    const float* inputs  = (const float*)d_in[1];
    const float* en_W    = (const float*)d_in[2];
    const float* en_b    = (const float*)d_in[3];
    const float* down_r  = (const float*)d_in[4];
    const float* down_w  = (const float*)d_in[5];
    const float* mlp1_W1 = (const float*)d_in[6];
    const float* mlp1_b1 = (const float*)d_in[7];
    const float* mlp1_W2 = (const float*)d_in[8];
    const float* mlp1_b2 = (const float*)d_in[9];
    const float* w1_W    = (const float*)d_in[10];
    const float* w1_b    = (const float*)d_in[11];
    const float* pa_r    = (const float*)d_in[12];
    const float* pa_w    = (const float*)d_in[13];
    const float* blk_W1  = (const float*)d_in[14];
    const float* blk_b1  = (const float*)d_in[15];
    const float* blk_W2  = (const float*)d_in[16];
    const float* blk_b2  = (const float*)d_in[17];
    const float* wi_W    = (const float*)d_in[18];
    const float* wi_b    = (const float*)d_in[19];
    const float* up_r    = (const float*)d_in[20];
    const float* up_w    = (const float*)d_in[21];
    const float* mlp2_W1 = (const float*)d_in[22];
    const float* mlp2_b1 = (const float*)d_in[23];
    const float* mlp2_W2 = (const float*)d_in[24];
    const float* mlp2_b2 = (const float*)d_in[25];
    const float* w2_W    = (const float*)d_in[26];
    const float* w2_b    = (const float*)d_in[27];
    const float* de_W1   = (const float*)d_in[28];
    const float* de_b1   = (const float*)d_in[29];
    const float* de_W2   = (const float*)d_in[30];
    const float* de_b2   = (const float*)d_in[31];
    float* outp = (float*)d_out;

    float*  en = symf(g_en);
    float*  x  = symf(g_x);
    float*  hb = symf(g_h);
    float*  tb = symf(g_t);
    float*  rb = symf(g_r);
    float*  vb = symf(g_v);
    float*  wc = symf(g_wcat);
    float2* rsp;
    { void* p = nullptr; cudaGetSymbolAddress(&p, g_rowstats); rsp = (float2*)p; }

    cudaFuncSetAttribute(gemm3_kernel,  cudaFuncAttributeMaxDynamicSharedMemorySize, GEMM_SMEM);
    cudaFuncSetAttribute(gemm3p_kernel, cudaFuncAttributeMaxDynamicSharedMemorySize, GEMM_SMEM);
    cudaFuncSetAttribute(attn5_kernel<0>, cudaFuncAttributeMaxDynamicSharedMemorySize, ATTN_SMEM);
    cudaFuncSetAttribute(attn5_kernel<1>, cudaFuncAttributeMaxDynamicSharedMemorySize, ATTN_SMEM);

    dim3 ggrid(BN / 32, 2);
    dim3 pgrid(BN / 32, 2, 2);
    dim3 agrid(NN / 64, HH, BB);

    rowstats_kernel<<<BN / 8, 256>>>(md, rsp);
    enc_kernel<<<BN, HID>>>(inputs, en_W, en_b, en);

    // ---- stage 1 (input en, masked mhpa) ----
    repack_kernel<<<64, 256>>>(down_w, wc);
    gemm3p_kernel<<<pgrid, 256, GEMM_SMEM>>>(en, wc, vb, w1_W, w1_b, rb);
    attn5_kernel<1><<<agrid, 512, ATTN_SMEM>>>(md, vb, down_r, rsp, hb);
    gemm3_kernel<<<ggrid, 256, GEMM_SMEM>>>(hb, mlp1_W1, mlp1_b1, nullptr, tb, 1);
    gemm3_kernel<<<ggrid, 256, GEMM_SMEM>>>(tb, mlp1_W2, mlp1_b2, rb, x, 1);

    // ---- 4 unmasked blocks ----
    for (int i = 0; i < 4; ++i) {
        repack_kernel<<<64, 256>>>(pa_w + (size_t)i * HH * HID * VD, wc);
        gemm3p_kernel<<<pgrid, 256, GEMM_SMEM>>>(x, wc, vb,
            wi_W + (size_t)i * HID * HID, wi_b + (size_t)i * HID, rb);
        attn5_kernel<0><<<agrid, 512, ATTN_SMEM>>>(md, vb, pa_r + (size_t)i * HH, rsp, hb);
        gemm3_kernel<<<ggrid, 256, GEMM_SMEM>>>(hb, blk_W1 + (size_t)i * HID * HID, blk_b1 + (size_t)i * HID, nullptr, tb, 1);
        gemm3_kernel<<<ggrid, 256, GEMM_SMEM>>>(tb, blk_W2 + (size_t)i * HID * HID, blk_b2 + (size_t)i * HID, rb, x, 1);
    }

    // ---- stage 2 (masked mhpa) ----
    repack_kernel<<<64, 256>>>(up_w, wc);
    gemm3p_kernel<<<pgrid, 256, GEMM_SMEM>>>(x, wc, vb, w2_W, w2_b, rb);
    attn5_kernel<1><<<agrid, 512, ATTN_SMEM>>>(md, vb, up_r, rsp, hb);
    gemm3_kernel<<<ggrid, 256, GEMM_SMEM>>>(hb, mlp2_W1, mlp2_b1, nullptr, tb, 1);
    gemm3_kernel<<<ggrid, 256, GEMM_SMEM>>>(tb, mlp2_W2, mlp2_b2, rb, x, 1);   // x = de

    // ---- decoder ----
    gemm3_kernel<<<ggrid, 256, GEMM_SMEM>>>(x, de_W1, de_b1, nullptr, tb, 1);
    final_kernel<<<BN / 8, 256>>>(tb, de_W2, de_b2, outp);
}

// round 7
// speedup vs baseline: 1.5791x; 1.1738x over previous
#include <cuda_runtime.h>
#include <math.h>

#define FULLMASK 0xffffffffu

#define BB   2
#define NN   2048
#define HH   8
#define HID  128
#define VD   16
#define BN   (BB * NN)
// locality=5 -> pos=0.05*2047=102.35 -> need 103rd smallest (0-indexed 102)
#define KTH  103

// GEMM smem: Ws [128][64] f32 (32KB) + As [32][128] f32 (16KB) = 48KB
#define GEMM_SMEM (32768 + 16384)
// Attention smem: full v, 2048 rows x stride-18 f32 = 144KB
#define ATTN_SMEM (NN * 18 * 4)

typedef unsigned long long ull;

// ---------------- scratch (device globals; no allocation) ----------------
__device__ float  g_en[BN * HID];
__device__ float  g_x [BN * HID];
__device__ float  g_h [BN * HID];
__device__ float  g_t [BN * HID];
__device__ float  g_r [BN * HID];
__device__ float  g_v [BN * HID];
__device__ float  g_wcat[HID * HID];
__device__ float2 g_rowstats[BN];

// ---------------- f32x2 packed helpers ----------------
__device__ __forceinline__ ull pack2(float x, float y) {
    ull r;
    asm("mov.b64 %0, {%1, %2};" : "=l"(r) : "r"(__float_as_uint(x)), "r"(__float_as_uint(y)));
    return r;
}
__device__ __forceinline__ void unpack2(ull u, float& x, float& y) {
    unsigned a, b;
    asm("mov.b64 {%0, %1}, %2;" : "=r"(a), "=r"(b) : "l"(u));
    x = __uint_as_float(a); y = __uint_as_float(b);
}
__device__ __forceinline__ ull fma2(ull a, ull b, ull c) {
    ull d;
    asm("fma.rn.f32x2 %0, %1, %2, %3;" : "=l"(d) : "l"(a), "l"(b), "l"(c));
    return d;
}
__device__ __forceinline__ ull add2(ull a, ull b) {
    ull d;
    asm("add.rn.f32x2 %0, %1, %2;" : "=l"(d) : "l"(a), "l"(b));
    return d;
}
__device__ __forceinline__ float ex2f(float x) {
    float r;
    asm("ex2.approx.f32 %0, %1;" : "=f"(r) : "f"(x));
    return r;
}

__device__ __forceinline__ float gelu_f(float x) {
    // exact (erf) gelu, matching jax.nn.gelu(approximate=False)
    return 0.5f * x * (1.0f + erff(x * 0.70710678118654752f));
}

// ---------------- per-row order statistics of m_dist ----------------
__global__ void rowstats_kernel(const float* __restrict__ md, float2* __restrict__ rs) {
    int warp = threadIdx.x >> 5, lane = threadIdx.x & 31;
    int row = blockIdx.x * 8 + warp;
    const float* p = md + (size_t)row * NN + lane;
    unsigned mu[64];
    float mn = 1e30f;
#pragma unroll
    for (int i = 0; i < 64; ++i) {
        float x = p[i * 32];
        mn = fminf(mn, x);
        mu[i] = __float_as_uint(x);
    }
#pragma unroll
    for (int off = 16; off; off >>= 1)
        mn = fminf(mn, __shfl_xor_sync(FULLMASK, mn, off));

    unsigned lo = 0u, hi = 0x3F800000u;  // bit patterns of [0,1)
    while (hi - lo > 1u) {
        unsigned mid = (lo + hi) >> 1;
        int c = 0;
#pragma unroll
        for (int i = 0; i < 64; ++i) c += (mu[i] <= mid) ? 1 : 0;
        c = __reduce_add_sync(FULLMASK, c);
        if (c >= KTH) hi = mid; else lo = mid;
    }
    if (lane == 0) rs[row] = make_float2(mn, __uint_as_float(hi));
}

// ---------------- encoder: gelu(inputs @ en_W + en_b), K=3 ----------------
__global__ void enc_kernel(const float* __restrict__ inp, const float* __restrict__ W,
                           const float* __restrict__ bvec, float* __restrict__ out) {
    int token = blockIdx.x, c = threadIdx.x;
    float x0 = inp[token * 3 + 0];
    float x1 = inp[token * 3 + 1];
    float x2 = inp[token * 3 + 2];
    float s = bvec[c];
    s = fmaf(x0, W[c], s);
    s = fmaf(x1, W[HID + c], s);
    s = fmaf(x2, W[2 * HID + c], s);
    out[(size_t)token * HID + c] = gelu_f(s);
}

// ---------------- repack head weights (H,HID,VD) -> (HID, H*VD) ----------------
__global__ void repack_kernel(const float* __restrict__ w, float* __restrict__ wc) {
    int idx = blockIdx.x * 256 + threadIdx.x;  // 16384 total
    int k = idx >> 7, c = idx & 127;
    wc[idx] = w[(c >> 4) * (HID * VD) + k * VD + (c & 15)];
}

// ---------------- GEMM body: 32 rows x 64 cols per CTA ----------------
__device__ __forceinline__ void gemm3_body(
    const float* __restrict__ A, const float* __restrict__ W,
    const float* __restrict__ bias, const float* __restrict__ res,
    float* __restrict__ out, int act, float* sm)
{
    float* Ws = sm;              // [128][64]
    float* As = sm + 128 * 64;   // [32][128]

    int tid = threadIdx.x, lane = tid & 31, warp = tid >> 5;
    int row0 = blockIdx.x * 32;
    int cbase = blockIdx.y * 64;

#pragma unroll
    for (int idx = tid; idx < 128 * 16; idx += 256) {
        int k = idx >> 4, q = idx & 15;
        *(float4*)(Ws + k * 64 + q * 4) = *(const float4*)(W + (size_t)k * HID + cbase + q * 4);
    }
#pragma unroll
    for (int idx = tid; idx < 32 * 32; idx += 256) {
        int r = idx >> 5, q = idx & 31;
        *(float4*)(As + r * HID + q * 4) = *(const float4*)(A + (size_t)(row0 + r) * HID + q * 4);
    }
    __syncthreads();

    ull acc[4] = {0ull, 0ull, 0ull, 0ull};
    const ull* Wu = (const ull*)Ws;          // [k][32]
    const float* a0 = As + warp * 4 * HID;

#pragma unroll 8
    for (int k = 0; k < HID; ++k) {
        ull wp = Wu[k * 32 + lane];
        float x0 = a0[0 * HID + k];
        float x1 = a0[1 * HID + k];
        float x2 = a0[2 * HID + k];
        float x3 = a0[3 * HID + k];
        acc[0] = fma2(pack2(x0, x0), wp, acc[0]);
        acc[1] = fma2(pack2(x1, x1), wp, acc[1]);
        acc[2] = fma2(pack2(x2, x2), wp, acc[2]);
        acc[3] = fma2(pack2(x3, x3), wp, acc[3]);
    }

    float b0 = 0.f, b1 = 0.f;
    if (bias) {
        float2 bv = *(const float2*)(bias + cbase + 2 * lane);
        b0 = bv.x; b1 = bv.y;
    }
#pragma unroll
    for (int i = 0; i < 4; ++i) {
        int row = row0 + warp * 4 + i;
        float o0, o1;
        unpack2(acc[i], o0, o1);
        o0 += b0; o1 += b1;
        if (res) {
            float2 rv = *(const float2*)(res + (size_t)row * HID + cbase + 2 * lane);
            o0 += rv.x; o1 += rv.y;
        }
        if (act) { o0 = gelu_f(o0); o1 = gelu_f(o1); }
        *(float2*)(out + (size_t)row * HID + cbase + 2 * lane) = make_float2(o0, o1);
    }
}

__global__ void __launch_bounds__(256) gemm3_kernel(
    const float* __restrict__ A, const float* __restrict__ W,
    const float* __restrict__ bias, const float* __restrict__ res,
    float* __restrict__ out, int act)
{
    extern __shared__ float sm[];
    gemm3_body(A, W, bias, res, out, act, sm);
}

// paired GEMM: two weight sets on the same A, selected by blockIdx.z.
__global__ void __launch_bounds__(256) gemm3p_kernel(
    const float* __restrict__ A,
    const float* __restrict__ W0, float* __restrict__ out0,
    const float* __restrict__ W1, const float* __restrict__ b1,
    float* __restrict__ out1)
{
    extern __shared__ float sm[];
    if (blockIdx.z == 0) gemm3_body(A, W0, nullptr, nullptr, out0, 0, sm);
    else                 gemm3_body(A, W1, b1,      nullptr, out1, 0, sm);
}

// ---------------- fused percentile-softmax attention + gelu ----------------
// CTA: 512 threads = 16 warps x 2 rows = 32 rows, one (b,h). Full v (2048x16)
// in smem, stride 18 (conflict-free LDS.64: half-warp bank-pairs distinct).
// Lane <-> j. Depth-4 prefetch ring on m_dist (L2 latency ~260cyc) AND
// one-step software pipeline on the v LDS loads (29cyc LDS latency).
// exp once per (i,j); 16 dims as 8 packed f32x2 FMAs; wsum packed pair.
template <int MASKED>
__global__ void __launch_bounds__(512, 1) attn6_kernel(
    const float* __restrict__ md, const float* __restrict__ v,
    const float* __restrict__ rvec, const float2* __restrict__ rs,
    float* __restrict__ out)
{
    extern __shared__ float vs[];   // [2048][18]
    int b = blockIdx.z, h = blockIdx.y;
    float rr = rvec[h];
    float r2 = rr * rr;
    const float L2E = 1.4426950408889634f;
    float nr2l = -r2 * L2E;

    int tid = threadIdx.x;
    int lane = tid & 31, warp = tid >> 5;
    int i0 = blockIdx.x * 32 + warp * 2;

    // stage full v_h into smem
    const float* vg = v + (size_t)b * NN * HID + h * VD;
    for (int idx = tid; idx < NN * 8; idx += 512) {
        int jj = idx >> 3, dd = (idx & 7) << 1;
        float2 val = *(const float2*)(vg + (size_t)jj * HID + dd);
        *(float2*)(vs + jj * 18 + dd) = val;
    }

    float msdl[2], s102[2];
    ull wsum2 = 0ull;              // packed (wsum0, wsum1)
    ull acc[2][8];
#pragma unroll
    for (int g = 0; g < 2; ++g) {
        float2 st = rs[b * NN + i0 + g];
        msdl[g] = (st.x * r2) * L2E;  // st.x*r2 == min_j(sd) exactly (monotone)
        s102[g] = st.y;
#pragma unroll
        for (int d = 0; d < 8; ++d) acc[g][d] = 0ull;
    }

    const float* mrow = md + ((size_t)b * NN + i0) * NN + lane;

    __syncthreads();

    // prime depth-4 m prefetch ring
    float mr[2][4];
#pragma unroll
    for (int d = 0; d < 4; ++d) {
        mr[0][d] = mrow[0 * (size_t)NN + 32 * d];
        mr[1][d] = mrow[1 * (size_t)NN + 32 * d];
    }

    // prime v pipeline: load step 0's v row
    const ull* vp = (const ull*)(vs + lane * 18);
    ull v0 = vp[0], v1 = vp[1], v2 = vp[2], v3 = vp[3];
    ull v4 = vp[4], v5 = vp[5], v6 = vp[6], v7 = vp[7];

#pragma unroll 4
    for (int t = 0; t < NN / 32; ++t) {
        int slot = t & 3;
        float m0 = mr[0][slot];
        float m1 = mr[1][slot];

        // prefetch m for step t+4 (clamped; redundant tail prefetches unused)
        int tp = t + 4; if (tp > NN / 32 - 1) tp = NN / 32 - 1;
        mr[0][slot] = mrow[0 * (size_t)NN + 32 * tp];
        mr[1][slot] = mrow[1 * (size_t)NN + 32 * tp];

        // prefetch v for step t+1 (clamped)
        int jn = lane + 32 * (t + 1); if (jn >= NN) jn = lane;
        const ull* vn = (const ull*)(vs + jn * 18);
        ull n0 = vn[0], n1 = vn[1], n2 = vn[2], n3 = vn[3];
        ull n4 = vn[4], n5 = vn[5], n6 = vn[6], n7 = vn[7];

        float e0 = ex2f(fmaf(m0, nr2l, msdl[0]));
        float e1 = ex2f(fmaf(m1, nr2l, msdl[1]));
        float w0 = MASKED ? ((m0 <= s102[0]) ? e0 : 0.f) : e0;
        float w1 = MASKED ? ((m1 <= s102[1]) ? e1 : 0.f) : e1;
        wsum2 = add2(wsum2, pack2(w0, w1));
        ull wp0 = pack2(w0, w0);
        ull wp1 = pack2(w1, w1);

        acc[0][0] = fma2(wp0, v0, acc[0][0]);
        acc[0][1] = fma2(wp0, v1, acc[0][1]);
        acc[0][2] = fma2(wp0, v2, acc[0][2]);
        acc[0][3] = fma2(wp0, v3, acc[0][3]);
        acc[0][4] = fma2(wp0, v4, acc[0][4]);
        acc[0][5] = fma2(wp0, v5, acc[0][5]);
        acc[0][6] = fma2(wp0, v6, acc[0][6]);
        acc[0][7] = fma2(wp0, v7, acc[0][7]);

        acc[1][0] = fma2(wp1, v0, acc[1][0]);
        acc[1][1] = fma2(wp1, v1, acc[1][1]);
        acc[1][2] = fma2(wp1, v2, acc[1][2]);
        acc[1][3] = fma2(wp1, v3, acc[1][3]);
        acc[1][4] = fma2(wp1, v4, acc[1][4]);
        acc[1][5] = fma2(wp1, v5, acc[1][5]);
        acc[1][6] = fma2(wp1, v6, acc[1][6]);
        acc[1][7] = fma2(wp1, v7, acc[1][7]);

        v0 = n0; v1 = n1; v2 = n2; v3 = n3;
        v4 = n4; v5 = n5; v6 = n6; v7 = n7;
    }

    // butterfly reduce across 32 lanes (j slots)
    float wsum[2];
    unpack2(wsum2, wsum[0], wsum[1]);
#pragma unroll
    for (int off = 16; off; off >>= 1) {
#pragma unroll
        for (int g = 0; g < 2; ++g) {
            wsum[g] += __shfl_xor_sync(FULLMASK, wsum[g], off);
#pragma unroll
            for (int d = 0; d < 8; ++d) {
                ull o = __shfl_xor_sync(FULLMASK, acc[g][d], off);
                acc[g][d] = add2(acc[g][d], o);
            }
        }
    }

    if (lane < 2) {
        int g = lane;
        float inv = 1.0f / wsum[g];
        float o[16];
#pragma unroll
        for (int d = 0; d < 8; ++d) unpack2(acc[g][d], o[2 * d], o[2 * d + 1]);
#pragma unroll
        for (int e = 0; e < 16; ++e) o[e] = gelu_f(o[e] * inv);
        float* dst = out + (size_t)(b * NN + i0 + g) * HID + h * VD;
        *(float4*)(dst + 0)  = make_float4(o[0],  o[1],  o[2],  o[3]);
        *(float4*)(dst + 4)  = make_float4(o[4],  o[5],  o[6],  o[7]);
        *(float4*)(dst + 8)  = make_float4(o[8],  o[9],  o[10], o[11]);
        *(float4*)(dst + 12) = make_float4(o[12], o[13], o[14], o[15]);
    }
}

// ---------------- final 128 -> 1 projection ----------------
__global__ void final_kernel(const float* __restrict__ t, const float* __restrict__ W,
                             const float* __restrict__ bvec, float* __restrict__ out) {
    int warp = threadIdx.x >> 5, lane = threadIdx.x & 31;
    int token = blockIdx.x * 8 + warp;
    const float* p = t + (size_t)token * HID;
    float s = 0.f;
#pragma unroll
    for (int i = 0; i < 4; ++i) s = fmaf(p[lane + 32 * i], W[lane + 32 * i], s);
#pragma unroll
    for (int off = 16; off; off >>= 1) s += __shfl_xor_sync(FULLMASK, s, off);
    if (lane == 0) out[token] = s + bvec[0];
}

// ---------------- orchestration ----------------
static float* symf(const void* sym) {
    void* p = nullptr;
    cudaGetSymbolAddress(&p, sym);
    return (float*)p;
}

extern "C" void kernel_launch(void* const* d_in, const int* in_sizes, int n_in,
                              void* d_out, int out_size) {
    const float* md      = (const float*)d_in[0];
    const float* inputs  = (const float*)d_in[1];
    const float* en_W    = (const float*)d_in[2];
    const float* en_b    = (const float*)d_in[3];
    const float* down_r  = (const float*)d_in[4];
    const float* down_w  = (const float*)d_in[5];
    const float* mlp1_W1 = (const float*)d_in[6];
    const float* mlp1_b1 = (const float*)d_in[7];
    const float* mlp1_W2 = (const float*)d_in[8];
    const float* mlp1_b2 = (const float*)d_in[9];
    const float* w1_W    = (const float*)d_in[10];
    const float* w1_b    = (const float*)d_in[11];
    const float* pa_r    = (const float*)d_in[12];
    const float* pa_w    = (const float*)d_in[13];
    const float* blk_W1  = (const float*)d_in[14];
    const float* blk_b1  = (const float*)d_in[15];
    const float* blk_W2  = (const float*)d_in[16];
    const float* blk_b2  = (const float*)d_in[17];
    const float* wi_W    = (const float*)d_in[18];
    const float* wi_b    = (const float*)d_in[19];
    const float* up_r    = (const float*)d_in[20];
    const float* up_w    = (const float*)d_in[21];
    const float* mlp2_W1 = (const float*)d_in[22];
    const float* mlp2_b1 = (const float*)d_in[23];
    const float* mlp2_W2 = (const float*)d_in[24];
    const float* mlp2_b2 = (const float*)d_in[25];
    const float* w2_W    = (const float*)d_in[26];
    const float* w2_b    = (const float*)d_in[27];
    const float* de_W1   = (const float*)d_in[28];
    const float* de_b1   = (const float*)d_in[29];
    const float* de_W2   = (const float*)d_in[30];
    const float* de_b2   = (const float*)d_in[31];
    float* outp = (float*)d_out;

    float*  en = symf(g_en);
    float*  x  = symf(g_x);
    float*  hb = symf(g_h);
    float*  tb = symf(g_t);
    float*  rb = symf(g_r);
    float*  vb = symf(g_v);
    float*  wc = symf(g_wcat);
    float2* rsp;
    { void* p = nullptr; cudaGetSymbolAddress(&p, g_rowstats); rsp = (float2*)p; }

    cudaFuncSetAttribute(gemm3_kernel,  cudaFuncAttributeMaxDynamicSharedMemorySize, GEMM_SMEM);
    cudaFuncSetAttribute(gemm3p_kernel, cudaFuncAttributeMaxDynamicSharedMemorySize, GEMM_SMEM);
    cudaFuncSetAttribute(attn6_kernel<0>, cudaFuncAttributeMaxDynamicSharedMemorySize, ATTN_SMEM);
    cudaFuncSetAttribute(attn6_kernel<1>, cudaFuncAttributeMaxDynamicSharedMemorySize, ATTN_SMEM);

    dim3 ggrid(BN / 32, 2);
    dim3 pgrid(BN / 32, 2, 2);
    dim3 agrid(NN / 32, HH, BB);

    rowstats_kernel<<<BN / 8, 256>>>(md, rsp);
    enc_kernel<<<BN, HID>>>(inputs, en_W, en_b, en);

    // ---- stage 1 (input en, masked mhpa) ----
    repack_kernel<<<64, 256>>>(down_w, wc);
    gemm3p_kernel<<<pgrid, 256, GEMM_SMEM>>>(en, wc, vb, w1_W, w1_b, rb);
    attn6_kernel<1><<<agrid, 512, ATTN_SMEM>>>(md, vb, down_r, rsp, hb);
    gemm3_kernel<<<ggrid, 256, GEMM_SMEM>>>(hb, mlp1_W1, mlp1_b1, nullptr, tb, 1);
    gemm3_kernel<<<ggrid, 256, GEMM_SMEM>>>(tb, mlp1_W2, mlp1_b2, rb, x, 1);

    // ---- 4 unmasked blocks ----
    for (int i = 0; i < 4; ++i) {
        repack_kernel<<<64, 256>>>(pa_w + (size_t)i * HH * HID * VD, wc);
        gemm3p_kernel<<<pgrid, 256, GEMM_SMEM>>>(x, wc, vb,
            wi_W + (size_t)i * HID * HID, wi_b + (size_t)i * HID, rb);
        attn6_kernel<0><<<agrid, 512, ATTN_SMEM>>>(md, vb, pa_r + (size_t)i * HH, rsp, hb);
        gemm3_kernel<<<ggrid, 256, GEMM_SMEM>>>(hb, blk_W1 + (size_t)i * HID * HID, blk_b1 + (size_t)i * HID, nullptr, tb, 1);
        gemm3_kernel<<<ggrid, 256, GEMM_SMEM>>>(tb, blk_W2 + (size_t)i * HID * HID, blk_b2 + (size_t)i * HID, rb, x, 1);
    }

    // ---- stage 2 (masked mhpa) ----
    repack_kernel<<<64, 256>>>(up_w, wc);
    gemm3p_kernel<<<pgrid, 256, GEMM_SMEM>>>(x, wc, vb, w2_W, w2_b, rb);
    attn6_kernel<1><<<agrid, 512, ATTN_SMEM>>>(md, vb, up_r, rsp, hb);
    gemm3_kernel<<<ggrid, 256, GEMM_SMEM>>>(hb, mlp2_W1, mlp2_b1, nullptr, tb, 1);
    gemm3_kernel<<<ggrid, 256, GEMM_SMEM>>>(tb, mlp2_W2, mlp2_b2, rb, x, 1);   // x = de

    // ---- decoder ----
    gemm3_kernel<<<ggrid, 256, GEMM_SMEM>>>(x, de_W1, de_b1, nullptr, tb, 1);
    final_kernel<<<BN / 8, 256>>>(tb, de_W2, de_b2, outp);
}